// round 11
// baseline (speedup 1.0000x reference)
#include <cuda_runtime.h>
#include <cstdint>
#include <cstddef>

#define NN 8192
#define RWD 10
#define HD1 100
#define HD2 100
#define NB_SEG 256

#define MSPLIT 32
#define MW 64                       // m-window per stage
#define ROWSB 128                   // rows per block (32 lanes x 4)
#define ITERS ((NN / MSPLIT) / MW)  // 4
#define HOP_TILE_BYTES (ROWSB * MW * 4)   // 32768
#define X_TILE_BYTES (MW * RWD * 4)       // 2560
// triple-buffered: depth-2 prefetch (proven best R8/R10)
#define SMEM_A_BYTES (3 * (HOP_TILE_BYTES + X_TILE_BYTES))  // 105984 -> 2 blocks/SM

typedef unsigned long long u64;

// ---------------- scratch (static device arrays; no allocation) ----------------
__device__ float g_part[3 * MSPLIT * NN * RWD];  // per-m-split partials (31.4MB)
__device__ float g_nodeout[4 * NN * HD2];        // per-(k, node) MLP output (13.1MB)

// ---------------- helpers ----------------
__device__ __forceinline__ void fma2(u64 &acc, u64 a, u64 b) {
    asm("fma.rn.f32x2 %0, %1, %2, %0;" : "+l"(acc) : "l"(a), "l"(b));
}
__device__ __forceinline__ u64 pack2(float x, float y) {
    u64 r; asm("mov.b64 %0, {%1, %2};" : "=l"(r) : "f"(x), "f"(y)); return r;
}
__device__ __forceinline__ float2 unpack2(u64 v) {
    float2 r; asm("mov.b64 {%0, %1}, %2;" : "=f"(r.x), "=f"(r.y) : "l"(v)); return r;
}
__device__ __forceinline__ void cp_async16(uint32_t dst, const void* src) {
    asm volatile("cp.async.cg.shared.global [%0], [%1], 16;" :: "r"(dst), "l"(src));
}
__device__ __forceinline__ void cp_commit() { asm volatile("cp.async.commit_group;"); }
template<int N> __device__ __forceinline__ void cp_wait() {
    asm volatile("cp.async.wait_group %0;" :: "n"(N));
}

// =====================================================================
// Kernel A: partial hopX over this block's m-range (256 m of one hop).
// Triple-buffered cp.async (depth-2 prefetch), 2 blocks/SM.
// MSPLIT=32 -> 6144 blocks: halved block time, ~1/4 the wave-tail loss.
// =====================================================================
extern "C" __global__ void __launch_bounds__(256, 2)
hop_gemv_kernel(const float* __restrict__ hop0, const float* __restrict__ hop1,
                const float* __restrict__ hop2, const float* __restrict__ X)
{
    extern __shared__ char smem[];
    char* hop_s = smem;                                   // 3 x 32KB
    char* x_s   = smem + 3 * HOP_TILE_BYTES;              // 3 x 2.5KB

    const int b   = blockIdx.x;                  // 6144 blocks
    const int k   = b >> 11;                     // 0..2
    const int rem = b & 2047;
    const int rg  = rem >> 5;                    // row group 0..63
    const int sp  = rem & 31;                    // m split 0..31
    const int row0   = rg * ROWSB;
    const int m_base = sp * (NN / MSPLIT);
    const float* hop = (k == 0) ? hop0 : (k == 1) ? hop1 : hop2;

    const int t = threadIdx.x;
    const int w = t >> 5, l = t & 31;

    const int tr = t >> 4;                    // 0..15
    const int tc = t & 15;                    // float4 column 0..15
    const int slotS = tc ^ (tr & 7);
    const char* gsrc0 = (const char*)(hop + (size_t)(row0 + tr) * NN + m_base + tc * 4);
    const uint32_t hdst0 = (uint32_t)__cvta_generic_to_shared(hop_s)
                         + (uint32_t)((tr * 16 + slotS) * 16);
    const char* xsrc0 = (const char*)(X + (size_t)m_base * RWD);
    const uint32_t xdst0 = (uint32_t)__cvta_generic_to_shared(x_s) + (uint32_t)(t * 16);

    auto stage = [&](int buf, int it) {
        const char* gs = gsrc0 + (size_t)it * (MW * 4);
        uint32_t hd = hdst0 + buf * HOP_TILE_BYTES;
        #pragma unroll
        for (int i = 0; i < 8; i++)
            cp_async16(hd + i * 4096, gs + (size_t)i * (16 * NN * 4));
        if (t < 160)
            cp_async16(xdst0 + buf * X_TILE_BYTES, xsrc0 + (size_t)it * X_TILE_BYTES + t * 16);
        cp_commit();
    };

    u64 acc[4][5];
    #pragma unroll
    for (int g = 0; g < 4; g++)
        #pragma unroll
        for (int p = 0; p < 5; p++) acc[g][p] = 0ull;

    stage(0, 0);
    stage(1, 1);

    int bc = 2;
    #pragma unroll 1
    for (int it = 0; it < ITERS; it++) {
        __syncthreads();                    // compute(it-1) done -> buffer free
        if (it + 2 < ITERS) {
            stage(bc, it + 2);
            bc = (bc == 2) ? 0 : bc + 1;
            cp_wait<2>();
        } else if (it + 1 < ITERS) cp_wait<1>();
        else                       cp_wait<0>();
        __syncthreads();                    // buffer it visible to all warps

        const float4* hb = (const float4*)(hop_s + (it % 3) * HOP_TILE_BYTES);
        const u64*    xb = (const u64*)(x_s + (it % 3) * X_TILE_BYTES);

        #pragma unroll
        for (int q = 0; q < 2; q++) {
            const int c4   = (w << 1) + q;          // 0..15
            const int slot = c4 ^ (l & 7);
            float4 h4[4];
            #pragma unroll
            for (int g = 0; g < 4; g++)
                h4[g] = hb[((l + (g << 5)) << 4) + slot];
            const u64* xp = xb + c4 * 20;
            #pragma unroll
            for (int j = 0; j < 4; j++) {
                const float* hv0 = (const float*)&h4[0];
                const float* hv1 = (const float*)&h4[1];
                const float* hv2 = (const float*)&h4[2];
                const float* hv3 = (const float*)&h4[3];
                u64 A0 = pack2(hv0[j], hv0[j]);
                u64 A1 = pack2(hv1[j], hv1[j]);
                u64 A2 = pack2(hv2[j], hv2[j]);
                u64 A3 = pack2(hv3[j], hv3[j]);
                #pragma unroll
                for (int p = 0; p < 5; p++) {
                    u64 xv = xp[j * 5 + p];
                    fma2(acc[0][p], A0, xv);
                    fma2(acc[1][p], A1, xv);
                    fma2(acc[2][p], A2, xv);
                    fma2(acc[3][p], A3, xv);
                }
            }
        }
    }

    float* red = (float*)smem;
    __syncthreads();
    #pragma unroll
    for (int g = 0; g < 4; g++) {
        int row = l + (g << 5);
        #pragma unroll
        for (int p = 0; p < 5; p++) {
            float2 v = unpack2(acc[g][p]);
            red[(w * ROWSB + row) * RWD + 2 * p]     = v.x;
            red[(w * ROWSB + row) * RWD + 2 * p + 1] = v.y;
        }
    }
    __syncthreads();
    for (int f = t; f < ROWSB * RWD; f += 256) {
        int row = f / RWD, d = f % RWD;
        float s = 0.f;
        #pragma unroll
        for (int ww = 0; ww < 8; ww++) s += red[(ww * ROWSB + row) * RWD + d];
        g_part[((size_t)(k * MSPLIT + sp) * NN + row0 + row) * RWD + d] = s;
    }
}

// =====================================================================
// Kernel B: k-split MLP. Grid = 256 node-tiles x 4 k. Each block handles
// ONE (tile, k): stage W2[k] once (no double buffer), gather input, phase1
// (register-tiled W1), phase2 (8 nodes/warp), write g_nodeout[k] plane.
// No k-loop -> 4x more, 4x shorter blocks; latency overlapped across blocks.
// =====================================================================
#define W2S_BYTES 40000
#define SMEM_H_OFF   40064
#define SMEM_INP_OFF 65664
#define SMEM_MLP_BYTES 66944

extern "C" __global__ void __launch_bounds__(256, 2)
mlp_kernel(const float* __restrict__ X, const float* __restrict__ W1,
           const float* __restrict__ b1, const float* __restrict__ W2,
           const float* __restrict__ b2)
{
    extern __shared__ char smemb[];
    u64*   hsm2 = (u64*)(smemb + SMEM_H_OFF);     // [32][100] (h,h) pairs
    float* inp  = (float*)(smemb + SMEM_INP_OFF); // [320]

    const int t = threadIdx.x;
    const int w = t >> 5, l = t & 31;
    const int bb = blockIdx.x;               // 1024 blocks
    const int node0 = (bb >> 2) * 32;
    const int k = bb & 3;

    // ---- stage W2[k] (single buffer) ----
    {
        const float4* src = (const float4*)(W2 + k * 10000);  // 2500 x 16B
        uint32_t dst = (uint32_t)__cvta_generic_to_shared(smemb);
        #pragma unroll
        for (int i = 0; i < 9; i++)
            cp_async16(dst + (i * 256 + t) * 16, src + i * 256 + t);
        if (t < 196)
            cp_async16(dst + (2304 + t) * 16, src + 2304 + t);
        cp_commit();
    }

    // ---- input tile for this k ----
    if (k == 0) {
        for (int f = t; f < 320; f += 256) inp[f] = X[(size_t)node0 * RWD + f];
    } else {
        const float* base = g_part + ((size_t)(k - 1) * MSPLIT * NN + node0) * RWD;
        for (int f = t; f < 320; f += 256) {
            float s = 0.f;
            #pragma unroll
            for (int sp = 0; sp < MSPLIT; sp++)
                s += base[(size_t)sp * NN * RWD + f];
            inp[f] = s;
        }
    }
    __syncthreads();   // inp visible

    // ---- phase 1: warp = 4 nodes, lane<25 = j-quad ----
    if (l < 25) {
        const float* w1k = W1 + k * 1000;
        ulonglong2 w1p[10];
        #pragma unroll
        for (int r = 0; r < 10; r++)
            w1p[r] = *(const ulonglong2*)(w1k + r * 100 + 4 * l);
        float4 b1q = *(const float4*)(b1 + k * 100 + 4 * l);
        u64 binit0 = pack2(b1q.x, b1q.y), binit1 = pack2(b1q.z, b1q.w);
        #pragma unroll
        for (int nn = 0; nn < 4; nn++) {
            const int row = w * 4 + nn;
            u64 s0 = binit0, s1 = binit1;
            #pragma unroll
            for (int r = 0; r < 10; r++) {
                float xv = inp[row * 10 + r];   // broadcast
                u64 xp2 = pack2(xv, xv);
                fma2(s0, xp2, w1p[r].x);
                fma2(s1, xp2, w1p[r].y);
            }
            float2 a = unpack2(s0), bvv = unpack2(s1);
            float h0 = fmaxf(a.x, 0.f), h1 = fmaxf(a.y, 0.f);
            float h2 = fmaxf(bvv.x, 0.f), h3 = fmaxf(bvv.y, 0.f);
            ulonglong2 o01 = { pack2(h0, h0), pack2(h1, h1) };
            ulonglong2 o23 = { pack2(h2, h2), pack2(h3, h3) };
            *(ulonglong2*)&hsm2[row * 100 + 4 * l]     = o01;
            *(ulonglong2*)&hsm2[row * 100 + 4 * l + 2] = o23;
        }
    }
    cp_wait<0>();       // W2 staged
    __syncthreads();

    // ---- phase 2: warps 0-3, 8 nodes each; lane<25 = o-quad ----
    if (w < 4 && l < 25) {
        const float* w2f = (const float*)smemb;
        u64 acc[8][2];
        #pragma unroll
        for (int nn = 0; nn < 8; nn++) { acc[nn][0] = 0ull; acc[nn][1] = 0ull; }
        #pragma unroll 5
        for (int d4 = 0; d4 < 25; d4++) {
            u64 wq[4][2];
            #pragma unroll
            for (int j = 0; j < 4; j++) {
                ulonglong2 ww = *(const ulonglong2*)&w2f[(4 * d4 + j) * 100 + 4 * l];
                wq[j][0] = ww.x; wq[j][1] = ww.y;
            }
            #pragma unroll
            for (int nn = 0; nn < 8; nn++) {
                const int row = w * 8 + nn;
                ulonglong2 h01 = *(const ulonglong2*)&hsm2[row * 100 + 4 * d4];
                ulonglong2 h23 = *(const ulonglong2*)&hsm2[row * 100 + 4 * d4 + 2];
                fma2(acc[nn][0], h01.x, wq[0][0]); fma2(acc[nn][1], h01.x, wq[0][1]);
                fma2(acc[nn][0], h01.y, wq[1][0]); fma2(acc[nn][1], h01.y, wq[1][1]);
                fma2(acc[nn][0], h23.x, wq[2][0]); fma2(acc[nn][1], h23.x, wq[2][1]);
                fma2(acc[nn][0], h23.y, wq[3][0]); fma2(acc[nn][1], h23.y, wq[3][1]);
            }
        }
        // ---- output to this k's plane ----
        #pragma unroll
        for (int nn = 0; nn < 8; nn++) {
            int n = node0 + w * 8 + nn;
            float2 a0 = unpack2(acc[nn][0]);
            float2 a1 = unpack2(acc[nn][1]);
            float4 o4 = { a0.x, a0.y, a1.x, a1.y };
            *(float4*)&g_nodeout[((size_t)k * NN + n) * 100 + 4 * l] = o4;
        }
    }
}

// =====================================================================
// Kernel C: deterministic segment sum over nodes AND the 4 k-planes,
// plus (hi-lo) * sum_k b2.
// =====================================================================
__device__ __forceinline__ int lbound(const int* a, int n, int v) {
    int lo = 0, hi = n;
    while (lo < hi) { int mid = (lo + hi) >> 1; if (a[mid] < v) lo = mid + 1; else hi = mid; }
    return lo;
}

extern "C" __global__ void segpool_kernel(const int* __restrict__ bidx,
                                          const float* __restrict__ b2,
                                          float* __restrict__ out)
{
    const int b = blockIdx.x;
    const int lo = lbound(bidx, NN, b);
    const int hi = lbound(bidx, NN, b + 1);
    const int t = threadIdx.x;
    if (t < 100) {
        const float* p0 = g_nodeout + t;
        const float* p1 = g_nodeout + (size_t)NN * 100 + t;
        const float* p2 = g_nodeout + (size_t)2 * NN * 100 + t;
        const float* p3 = g_nodeout + (size_t)3 * NN * 100 + t;
        float s = 0.f;
        int n = lo;
        for (; n + 1 < hi; n += 2) {
            size_t o0 = (size_t)n * 100, o1 = (size_t)(n + 1) * 100;
            s += p0[o0] + p1[o0] + p2[o0] + p3[o0];
            s += p0[o1] + p1[o1] + p2[o1] + p3[o1];
        }
        for (; n < hi; n++) {
            size_t o0 = (size_t)n * 100;
            s += p0[o0] + p1[o0] + p2[o0] + p3[o0];
        }
        float bsum = b2[t] + b2[100 + t] + b2[200 + t] + b2[300 + t];
        out[b * 100 + t] = s + (float)(hi - lo) * bsum;
    }
}

// =====================================================================
extern "C" void kernel_launch(void* const* d_in, const int* in_sizes, int n_in,
                              void* d_out, int out_size)
{
    const float* X    = (const float*)d_in[0];   // walk_feats (8192,10)
    const float* hop1 = (const float*)d_in[1];
    const float* hop2 = (const float*)d_in[2];
    const float* hop3 = (const float*)d_in[3];
    const int*   bidx = (const int*)d_in[4];
    const float* W1   = (const float*)d_in[5];   // (4,10,100)
    const float* b1   = (const float*)d_in[6];   // (4,100)
    const float* W2   = (const float*)d_in[7];   // (4,100,100)
    const float* b2   = (const float*)d_in[8];   // (4,100)
    float* out = (float*)d_out;                  // (256,100)

    (void)in_sizes; (void)n_in; (void)out_size;

    cudaFuncSetAttribute(hop_gemv_kernel, cudaFuncAttributeMaxDynamicSharedMemorySize, SMEM_A_BYTES);
    cudaFuncSetAttribute(mlp_kernel,      cudaFuncAttributeMaxDynamicSharedMemorySize, SMEM_MLP_BYTES);

    hop_gemv_kernel<<<6144, 256, SMEM_A_BYTES>>>(hop1, hop2, hop3, X);
    mlp_kernel<<<1024, 256, SMEM_MLP_BYTES>>>(X, W1, b1, W2, b2);
    segpool_kernel<<<NB_SEG, 128>>>(bidx, b2, out);
}

// round 12
// speedup vs baseline: 1.0875x; 1.0875x over previous
#include <cuda_runtime.h>
#include <cstdint>
#include <cstddef>

#define NN 8192
#define RWD 10
#define HD1 100
#define HD2 100
#define NB_SEG 256

#define MSPLIT 16
#define MW 64                       // m-window per stage
#define ROWSB 128                   // rows per block (32 lanes x 4)
#define ITERS ((NN / MSPLIT) / MW)  // 8
#define HOP_TILE_BYTES (ROWSB * MW * 4)   // 32768
#define X_TILE_BYTES (MW * RWD * 4)       // 2560
// triple-buffered: depth-2 prefetch (proven best R8/R10)
#define SMEM_A_BYTES (3 * (HOP_TILE_BYTES + X_TILE_BYTES))  // 105984 -> 2 blocks/SM

typedef unsigned long long u64;

// ---------------- scratch (static device arrays; no allocation) ----------------
__device__ float g_part[3 * MSPLIT * NN * RWD];  // per-m-split partials of hopX
__device__ float g_nodeout[NN * HD2];            // per-node summed MLP output

// ---------------- helpers ----------------
__device__ __forceinline__ void fma2(u64 &acc, u64 a, u64 b) {
    asm("fma.rn.f32x2 %0, %1, %2, %0;" : "+l"(acc) : "l"(a), "l"(b));
}
__device__ __forceinline__ u64 pack2(float x, float y) {
    u64 r; asm("mov.b64 %0, {%1, %2};" : "=l"(r) : "f"(x), "f"(y)); return r;
}
__device__ __forceinline__ float2 unpack2(u64 v) {
    float2 r; asm("mov.b64 {%0, %1}, %2;" : "=f"(r.x), "=f"(r.y) : "l"(v)); return r;
}
__device__ __forceinline__ void cp_async16(uint32_t dst, const void* src) {
    asm volatile("cp.async.cg.shared.global [%0], [%1], 16;" :: "r"(dst), "l"(src));
}
__device__ __forceinline__ void cp_commit() { asm volatile("cp.async.commit_group;"); }
template<int N> __device__ __forceinline__ void cp_wait() {
    asm volatile("cp.async.wait_group %0;" :: "n"(N));
}

// =====================================================================
// Kernel A: partial hopX over this block's m-range (512 m of one hop).
// R10 configuration (best measured: 125.4us, 82.8% DRAM): MSPLIT=16,
// triple-buffered cp.async (depth-2 prefetch), 2 blocks/SM.
// =====================================================================
extern "C" __global__ void __launch_bounds__(256, 2)
hop_gemv_kernel(const float* __restrict__ hop0, const float* __restrict__ hop1,
                const float* __restrict__ hop2, const float* __restrict__ X)
{
    extern __shared__ char smem[];
    char* hop_s = smem;                                   // 3 x 32KB
    char* x_s   = smem + 3 * HOP_TILE_BYTES;              // 3 x 2.5KB

    const int b   = blockIdx.x;                  // 3072 blocks
    const int k   = b >> 10;                     // 0..2
    const int rem = b & 1023;
    const int rg  = rem >> 4;                    // row group 0..63
    const int sp  = rem & 15;                    // m split 0..15
    const int row0   = rg * ROWSB;
    const int m_base = sp * (NN / MSPLIT);
    const float* hop = (k == 0) ? hop0 : (k == 1) ? hop1 : hop2;

    const int t = threadIdx.x;
    const int w = t >> 5, l = t & 31;

    const int tr = t >> 4;                    // 0..15
    const int tc = t & 15;                    // float4 column 0..15
    const int slotS = tc ^ (tr & 7);
    const char* gsrc0 = (const char*)(hop + (size_t)(row0 + tr) * NN + m_base + tc * 4);
    const uint32_t hdst0 = (uint32_t)__cvta_generic_to_shared(hop_s)
                         + (uint32_t)((tr * 16 + slotS) * 16);
    const char* xsrc0 = (const char*)(X + (size_t)m_base * RWD);
    const uint32_t xdst0 = (uint32_t)__cvta_generic_to_shared(x_s) + (uint32_t)(t * 16);

    auto stage = [&](int buf, int it) {
        const char* gs = gsrc0 + (size_t)it * (MW * 4);
        uint32_t hd = hdst0 + buf * HOP_TILE_BYTES;
        #pragma unroll
        for (int i = 0; i < 8; i++)
            cp_async16(hd + i * 4096, gs + (size_t)i * (16 * NN * 4));
        if (t < 160)
            cp_async16(xdst0 + buf * X_TILE_BYTES, xsrc0 + (size_t)it * X_TILE_BYTES + t * 16);
        cp_commit();
    };

    u64 acc[4][5];
    #pragma unroll
    for (int g = 0; g < 4; g++)
        #pragma unroll
        for (int p = 0; p < 5; p++) acc[g][p] = 0ull;

    stage(0, 0);
    stage(1, 1);

    int bc = 2;
    #pragma unroll 1
    for (int it = 0; it < ITERS; it++) {
        __syncthreads();                    // compute(it-1) done -> buffer free
        if (it + 2 < ITERS) {
            stage(bc, it + 2);
            bc = (bc == 2) ? 0 : bc + 1;
            cp_wait<2>();
        } else if (it + 1 < ITERS) cp_wait<1>();
        else                       cp_wait<0>();
        __syncthreads();                    // buffer it visible to all warps

        const float4* hb = (const float4*)(hop_s + (it % 3) * HOP_TILE_BYTES);
        const u64*    xb = (const u64*)(x_s + (it % 3) * X_TILE_BYTES);

        #pragma unroll
        for (int q = 0; q < 2; q++) {
            const int c4   = (w << 1) + q;          // 0..15
            const int slot = c4 ^ (l & 7);
            float4 h4[4];
            #pragma unroll
            for (int g = 0; g < 4; g++)
                h4[g] = hb[((l + (g << 5)) << 4) + slot];
            const u64* xp = xb + c4 * 20;
            #pragma unroll
            for (int j = 0; j < 4; j++) {
                const float* hv0 = (const float*)&h4[0];
                const float* hv1 = (const float*)&h4[1];
                const float* hv2 = (const float*)&h4[2];
                const float* hv3 = (const float*)&h4[3];
                u64 A0 = pack2(hv0[j], hv0[j]);
                u64 A1 = pack2(hv1[j], hv1[j]);
                u64 A2 = pack2(hv2[j], hv2[j]);
                u64 A3 = pack2(hv3[j], hv3[j]);
                #pragma unroll
                for (int p = 0; p < 5; p++) {
                    u64 xv = xp[j * 5 + p];
                    fma2(acc[0][p], A0, xv);
                    fma2(acc[1][p], A1, xv);
                    fma2(acc[2][p], A2, xv);
                    fma2(acc[3][p], A3, xv);
                }
            }
        }
    }

    float* red = (float*)smem;
    __syncthreads();
    #pragma unroll
    for (int g = 0; g < 4; g++) {
        int row = l + (g << 5);
        #pragma unroll
        for (int p = 0; p < 5; p++) {
            float2 v = unpack2(acc[g][p]);
            red[(w * ROWSB + row) * RWD + 2 * p]     = v.x;
            red[(w * ROWSB + row) * RWD + 2 * p + 1] = v.y;
        }
    }
    __syncthreads();
    for (int f = t; f < ROWSB * RWD; f += 256) {
        int row = f / RWD, d = f % RWD;
        float s = 0.f;
        #pragma unroll
        for (int ww = 0; ww < 8; ww++) s += red[(ww * ROWSB + row) * RWD + d];
        g_part[((size_t)(k * MSPLIT + sp) * NN + row0 + row) * RWD + d] = s;
    }
}

// =====================================================================
// Kernel B: node-parallel MLP, 256 blocks x 32 nodes. (R10 base)
// Change vs R10: h stored UNduplicated (float4, 1 LDS.128 per node per d4
// instead of 2); (h,h) operands built with pack2 in phase 2 (mov.b64 pairs
// that ptxas folds into register allocation). Halves h crossbar wavefronts.
// =====================================================================
#define W2S_BYTES 40000
#define SMEM_H_OFF   80000            // hsm: [32][100] float = 12800B
#define SMEM_INP_OFF 92800            // inp: 1280B
#define SMEM_B2_OFF  94080            // b2s: 400B
#define SMEM_MLP_BYTES 94592

extern "C" __global__ void __launch_bounds__(256, 2)
mlp_kernel(const float* __restrict__ X, const float* __restrict__ W1,
           const float* __restrict__ b1, const float* __restrict__ W2,
           const float* __restrict__ b2)
{
    extern __shared__ char smemb[];
    float* hsm  = (float*)(smemb + SMEM_H_OFF);   // [32][100] h (plain)
    float* inp  = (float*)(smemb + SMEM_INP_OFF); // [320]
    float* b2s  = (float*)(smemb + SMEM_B2_OFF);  // [100]

    const int t = threadIdx.x;
    const int w = t >> 5, l = t & 31;
    const int node0 = blockIdx.x * 32;

    const uint32_t w2base = (uint32_t)__cvta_generic_to_shared(smemb);

    auto stageW2 = [&](int buf, int k) {
        const float4* src = (const float4*)(W2 + k * 10000);  // 2500 x 16B
        uint32_t dst = w2base + buf * W2S_BYTES;
        #pragma unroll
        for (int i = 0; i < 9; i++)
            cp_async16(dst + (i * 256 + t) * 16, src + i * 256 + t);
        if (t < 196)
            cp_async16(dst + (2304 + t) * 16, src + 2304 + t);
        cp_commit();
    };

    if (t < 100) b2s[t] = b2[t] + b2[100 + t] + b2[200 + t] + b2[300 + t];

    stageW2(0, 0);
    stageW2(1, 1);

    u64 acc[8][2];
    #pragma unroll
    for (int nn = 0; nn < 8; nn++) { acc[nn][0] = 0ull; acc[nn][1] = 0ull; }

    #pragma unroll 1
    for (int k = 0; k < 4; k++) {
        // ---- input tile for this k ----
        if (k == 0) {
            for (int f = t; f < 320; f += 256) inp[f] = X[(size_t)node0 * RWD + f];
        } else {
            const float* base = g_part + ((size_t)(k - 1) * MSPLIT * NN + node0) * RWD;
            for (int f = t; f < 320; f += 256) {
                float s = 0.f;
                #pragma unroll
                for (int sp = 0; sp < MSPLIT; sp++)
                    s += base[(size_t)sp * NN * RWD + f];
                inp[f] = s;
            }
        }
        if (k < 3) cp_wait<1>(); else cp_wait<0>();
        __syncthreads();   // weights(k) + inp visible; hsm free

        // ---- phase 1: warp = 4 nodes, lane<25 = j-quad ----
        if (l < 25) {
            const float* w1k = W1 + k * 1000;
            ulonglong2 w1p[10];
            #pragma unroll
            for (int r = 0; r < 10; r++)
                w1p[r] = *(const ulonglong2*)(w1k + r * 100 + 4 * l);
            float4 b1q = *(const float4*)(b1 + k * 100 + 4 * l);
            u64 binit0 = pack2(b1q.x, b1q.y), binit1 = pack2(b1q.z, b1q.w);
            #pragma unroll
            for (int nn = 0; nn < 4; nn++) {
                const int row = w * 4 + nn;
                u64 s0 = binit0, s1 = binit1;
                #pragma unroll
                for (int r = 0; r < 10; r++) {
                    float xv = inp[row * 10 + r];   // broadcast
                    u64 xp2 = pack2(xv, xv);
                    fma2(s0, xp2, w1p[r].x);
                    fma2(s1, xp2, w1p[r].y);
                }
                float2 a = unpack2(s0), bvv = unpack2(s1);
                float4 hq = { fmaxf(a.x, 0.f), fmaxf(a.y, 0.f),
                              fmaxf(bvv.x, 0.f), fmaxf(bvv.y, 0.f) };
                *(float4*)&hsm[row * 100 + 4 * l] = hq;   // plain, 16B
            }
        }
        __syncthreads();

        // ---- phase 2: warps 0-3, 8 nodes each; lane<25 = o-quad ----
        if (w < 4 && l < 25) {
            const float* w2f = (const float*)(smemb + (k & 1) * W2S_BYTES);
            #pragma unroll 5
            for (int d4 = 0; d4 < 25; d4++) {
                u64 wq[4][2];
                #pragma unroll
                for (int j = 0; j < 4; j++) {
                    ulonglong2 ww = *(const ulonglong2*)&w2f[(4 * d4 + j) * 100 + 4 * l];
                    wq[j][0] = ww.x; wq[j][1] = ww.y;
                }
                #pragma unroll
                for (int nn = 0; nn < 8; nn++) {
                    const int row = w * 8 + nn;
                    float4 hq = *(const float4*)&hsm[row * 100 + 4 * d4];  // broadcast
                    u64 h0 = pack2(hq.x, hq.x);
                    u64 h1 = pack2(hq.y, hq.y);
                    u64 h2 = pack2(hq.z, hq.z);
                    u64 h3 = pack2(hq.w, hq.w);
                    fma2(acc[nn][0], h0, wq[0][0]); fma2(acc[nn][1], h0, wq[0][1]);
                    fma2(acc[nn][0], h1, wq[1][0]); fma2(acc[nn][1], h1, wq[1][1]);
                    fma2(acc[nn][0], h2, wq[2][0]); fma2(acc[nn][1], h2, wq[2][1]);
                    fma2(acc[nn][0], h3, wq[3][0]); fma2(acc[nn][1], h3, wq[3][1]);
                }
            }
        }
        __syncthreads();   // w2 buffer (k&1) free for restage
        if (k + 2 < 4) stageW2(k & 1, k + 2);
    }

    // ---- output: node_out = acc + sum_k b2 ----
    if (w < 4 && l < 25) {
        float4 bv = *(const float4*)&b2s[4 * l];
        #pragma unroll
        for (int nn = 0; nn < 8; nn++) {
            int n = node0 + w * 8 + nn;
            float2 a0 = unpack2(acc[nn][0]);
            float2 a1 = unpack2(acc[nn][1]);
            float4 o4 = { a0.x + bv.x, a0.y + bv.y, a1.x + bv.z, a1.y + bv.w };
            *(float4*)&g_nodeout[(size_t)n * 100 + 4 * l] = o4;
        }
    }
}

// =====================================================================
// Kernel C: deterministic segment sum via binary search on sorted batch_idx
// =====================================================================
__device__ __forceinline__ int lbound(const int* a, int n, int v) {
    int lo = 0, hi = n;
    while (lo < hi) { int mid = (lo + hi) >> 1; if (a[mid] < v) lo = mid + 1; else hi = mid; }
    return lo;
}

extern "C" __global__ void segpool_kernel(const int* __restrict__ bidx,
                                          float* __restrict__ out)
{
    const int b = blockIdx.x;
    const int lo = lbound(bidx, NN, b);
    const int hi = lbound(bidx, NN, b + 1);
    const int t = threadIdx.x;
    if (t < 100) {
        float s = 0.f;
        int n = lo;
        for (; n + 3 < hi; n += 4) {
            s += g_nodeout[(size_t)n * 100 + t];
            s += g_nodeout[(size_t)(n + 1) * 100 + t];
            s += g_nodeout[(size_t)(n + 2) * 100 + t];
            s += g_nodeout[(size_t)(n + 3) * 100 + t];
        }
        for (; n < hi; n++) s += g_nodeout[(size_t)n * 100 + t];
        out[b * 100 + t] = s;
    }
}

// =====================================================================
extern "C" void kernel_launch(void* const* d_in, const int* in_sizes, int n_in,
                              void* d_out, int out_size)
{
    const float* X    = (const float*)d_in[0];   // walk_feats (8192,10)
    const float* hop1 = (const float*)d_in[1];
    const float* hop2 = (const float*)d_in[2];
    const float* hop3 = (const float*)d_in[3];
    const int*   bidx = (const int*)d_in[4];
    const float* W1   = (const float*)d_in[5];   // (4,10,100)
    const float* b1   = (const float*)d_in[6];   // (4,100)
    const float* W2   = (const float*)d_in[7];   // (4,100,100)
    const float* b2   = (const float*)d_in[8];   // (4,100)
    float* out = (float*)d_out;                  // (256,100)

    (void)in_sizes; (void)n_in; (void)out_size;

    cudaFuncSetAttribute(hop_gemv_kernel, cudaFuncAttributeMaxDynamicSharedMemorySize, SMEM_A_BYTES);
    cudaFuncSetAttribute(mlp_kernel,      cudaFuncAttributeMaxDynamicSharedMemorySize, SMEM_MLP_BYTES);

    hop_gemv_kernel<<<3072, 256, SMEM_A_BYTES>>>(hop1, hop2, hop3, X);
    mlp_kernel<<<256, 256, SMEM_MLP_BYTES>>>(X, W1, b1, W2, b2);
    segpool_kernel<<<NB_SEG, 128>>>(bidx, out);
}